// round 1
// baseline (speedup 1.0000x reference)
#include <cuda_runtime.h>
#include <math.h>

// Shapes (fixed by the problem)
#define B 8
#define M 12
#define NN 32
#define D 256
#define C 1024      // N*N
#define CH 512      // C/R

// Scratch (allocation-free rule: device globals)
__device__ float g_ef[B * M * C];   // (bm, c)   e0 features
__device__ float g_cov[B * M * C];  // (bm, p)   covariance (sign -> mask)
__device__ float g_h[B * M * CH];   // (bm, o)   hidden after relu
__device__ float g_e2[B * M * C];   // (bm, c)   second GEMM out

// ---------------------------------------------------------------------------
// Kernel 1: per (b,m) tile: row sums/means, centered covariance (sign only
// needed downstream), and e0 = (S[n] + 2*S[k] - eq_sum(n,k)) / (2*D).
// x tile stored transposed+padded in smem: xst[d*33 + n] (conflict-free).
// Thread t (warp w, lane l) owns pairs (n = w + 8*i, k = l), i = 0..3.
// ---------------------------------------------------------------------------
__global__ void __launch_bounds__(256) k1_corr_e0(const float* __restrict__ x) {
    const int bm = blockIdx.x;
    __shared__ float xst[D * 33];
    __shared__ float S[NN];
    __shared__ float mu[NN];

    const int tid = threadIdx.x;
    const float* xt = x + (size_t)bm * (NN * D);

    // load transposed (coalesced global, conflict-free smem)
    for (int i = tid; i < NN * D; i += 256) {
        int n = i >> 8, d = i & 255;
        xst[d * 33 + n] = xt[i];
    }
    __syncthreads();

    const int w = tid >> 5, lane = tid & 31;

    // row sums: warp w handles rows 4w..4w+3
    for (int r = 0; r < 4; r++) {
        int n = w * 4 + r;
        float s = 0.f;
        #pragma unroll
        for (int j = 0; j < 8; j++) s += xst[(lane + 32 * j) * 33 + n];
        #pragma unroll
        for (int off = 16; off; off >>= 1) s += __shfl_xor_sync(0xffffffffu, s, off);
        if (lane == 0) { S[n] = s; mu[n] = s * (1.f / 256.f); }
    }
    __syncthreads();

    const float mk = mu[lane];
    const float Sk = S[lane];
    float mn[4], dotc[4] = {0.f, 0.f, 0.f, 0.f}, eq[4] = {0.f, 0.f, 0.f, 0.f};
    #pragma unroll
    for (int i = 0; i < 4; i++) mn[i] = mu[w + 8 * i];

    #pragma unroll 4
    for (int d = 0; d < D; d++) {
        const float xk  = xst[d * 33 + lane];   // conflict-free
        const float xck = xk - mk;
        #pragma unroll
        for (int i = 0; i < 4; i++) {
            const float xn = xst[d * 33 + w + 8 * i];  // broadcast
            dotc[i] += (xn - mn[i]) * xck;
            eq[i]   += (xn == xk) ? xk : 0.f;
        }
    }

    #pragma unroll
    for (int i = 0; i < 4; i++) {
        const int n = w + 8 * i;
        const int p = n * NN + lane;
        g_cov[bm * C + p] = dotc[i];
        g_ef[bm * C + p]  = (S[n] + 2.f * Sk - eq[i]) * (1.f / (2.f * D));
    }
}

// ---------------------------------------------------------------------------
// Kernel 2a: h[bm][o] = relu( sum_c W1[o][c] * ef[bm][c] )
// grid (16 o-tiles, 8 b), 384 threads: warp = one m (ef read is broadcast),
// lane = o within the 32-row tile (LDG.128 on W1).
// ---------------------------------------------------------------------------
__global__ void __launch_bounds__(384) k2a_gemm1(const float* __restrict__ W1) {
    const int ot = blockIdx.x, b = blockIdx.y;
    __shared__ float efs[M * C];  // 48 KB

    const int tid = threadIdx.x;
    const float* efb = g_ef + (size_t)b * M * C;
    for (int i = tid; i < M * C; i += 384) efs[i] = efb[i];
    __syncthreads();

    const int m = tid >> 5;          // warp id = m (12 warps)
    const int lane = tid & 31;
    const int o = ot * 32 + lane;

    const float4* w1row = (const float4*)(W1 + (size_t)o * C);
    const float4* efm   = (const float4*)(efs + m * C);

    float ax = 0.f, ay = 0.f, az = 0.f, aw = 0.f;
    #pragma unroll 8
    for (int c4 = 0; c4 < C / 4; c4++) {
        const float4 wv = w1row[c4];
        const float4 ev = efm[c4];   // all lanes same address: broadcast
        ax += wv.x * ev.x; ay += wv.y * ev.y;
        az += wv.z * ev.z; aw += wv.w * ev.w;
    }
    const float acc = (ax + ay) + (az + aw);
    g_h[((size_t)b * M + m) * CH + o] = fmaxf(acc, 0.f);
}

// ---------------------------------------------------------------------------
// Kernel 2b: e2[bm][c] = sum_o W2[c][o] * h[bm][o]
// grid (32 c-tiles, 8 b), 384 threads, same mapping.
// ---------------------------------------------------------------------------
__global__ void __launch_bounds__(384) k2b_gemm2(const float* __restrict__ W2) {
    const int ct = blockIdx.x, b = blockIdx.y;
    __shared__ float hs[M * CH];  // 24 KB

    const int tid = threadIdx.x;
    const float* hb = g_h + (size_t)b * M * CH;
    for (int i = tid; i < M * CH; i += 384) hs[i] = hb[i];
    __syncthreads();

    const int m = tid >> 5;
    const int lane = tid & 31;
    const int c = ct * 32 + lane;

    const float4* w2row = (const float4*)(W2 + (size_t)c * CH);
    const float4* hm    = (const float4*)(hs + m * CH);

    float ax = 0.f, ay = 0.f, az = 0.f, aw = 0.f;
    #pragma unroll 8
    for (int o4 = 0; o4 < CH / 4; o4++) {
        const float4 wv = w2row[o4];
        const float4 hv = hm[o4];
        ax += wv.x * hv.x; ay += wv.y * hv.y;
        az += wv.z * hv.z; aw += wv.w * hv.w;
    }
    g_e2[((size_t)b * M + m) * C + c] = (ax + ay) + (az + aw);
}

// ---------------------------------------------------------------------------
// Kernel 3: per (b,m): e = sigmoid(e2), mask by cov>0, row softmax,
// out[n][d] = sum_k att[n][k] * x[k][d].
// ---------------------------------------------------------------------------
__global__ void __launch_bounds__(256) k3_softmax_av(const float* __restrict__ x,
                                                     float* __restrict__ out) {
    const int bm = blockIdx.x;
    __shared__ float xs[NN * D];   // 32 KB, [k*256 + d]
    __shared__ float att[C];       // 4 KB

    const int tid = threadIdx.x;
    const float* xt = x + (size_t)bm * (NN * D);
    for (int i = tid; i < NN * D; i += 256) xs[i] = xt[i];

    for (int i = tid; i < C; i += 256) {
        const float cv = g_cov[bm * C + i];
        const float v  = g_e2[bm * C + i];
        const float e  = 1.f / (1.f + expf(-v));
        att[i] = (cv > 0.f) ? e : -1e12f;
    }
    __syncthreads();

    // softmax: warp w handles rows 4w..4w+3, lane = k
    const int w = tid >> 5, lane = tid & 31;
    for (int r = 0; r < 4; r++) {
        const int n = w * 4 + r;
        const float v = att[n * NN + lane];
        float mx = v;
        #pragma unroll
        for (int off = 16; off; off >>= 1) mx = fmaxf(mx, __shfl_xor_sync(0xffffffffu, mx, off));
        const float ev = expf(v - mx);
        float s = ev;
        #pragma unroll
        for (int off = 16; off; off >>= 1) s += __shfl_xor_sync(0xffffffffu, s, off);
        att[n * NN + lane] = ev / s;
    }
    __syncthreads();

    // out[n][tid] for all n: 32 accumulators, k inner loop
    const int d = tid;
    float acc[NN];
    #pragma unroll
    for (int n = 0; n < NN; n++) acc[n] = 0.f;

    for (int k = 0; k < NN; k++) {
        const float xv = xs[k * D + d];     // conflict-free
        #pragma unroll
        for (int n = 0; n < NN; n++)
            acc[n] += att[n * NN + k] * xv; // broadcast
    }

    float* ot = out + (size_t)bm * (NN * D);
    #pragma unroll
    for (int n = 0; n < NN; n++) ot[n * D + d] = acc[n];
}

// ---------------------------------------------------------------------------
extern "C" void kernel_launch(void* const* d_in, const int* in_sizes, int n_in,
                              void* d_out, int out_size) {
    const float* x  = (const float*)d_in[0];
    const float* W1 = (const float*)d_in[1];
    const float* W2 = (const float*)d_in[2];
    float* out = (float*)d_out;

    k1_corr_e0<<<B * M, 256>>>(x);
    k2a_gemm1<<<dim3(CH / 32, B), 384>>>(W1);
    k2b_gemm2<<<dim3(C / 32, B), 384>>>(W2);
    k3_softmax_av<<<B * M, 256>>>(x, out);
}

// round 2
// speedup vs baseline: 2.6956x; 2.6956x over previous
#include <cuda_runtime.h>
#include <math.h>

#define B 8
#define M 12
#define NN 32
#define D 256
#define C 1024      // N*N
#define CH 512      // C/R

// Scratch (allocation-free rule: device globals)
__device__ float g_ef[B * M * C];   // (bm, c)  e0 features
__device__ float g_cov[B * M * C];  // (bm, p)  raw-centered cov (sign -> mask)
__device__ float g_h[B * M * CH];   // (bm, o)  hidden after relu
__device__ float g_e2[B * M * C];   // (bm, c)  second GEMM out

// ---------------------------------------------------------------------------
// Kernel 1: per (b,m): row sums, covariance sign, e0 features.
// cov(n,k) sign == sign( dot(x_n,x_k) - S_n*S_k/D )  (norms are positive).
// e0(n,k) = (S[n] + 2*S[k] - eq(n,k)) / (2D),  eq = sum_{d: x_n[d]==x_k[d]} x_k[d].
// ---------------------------------------------------------------------------
__global__ void __launch_bounds__(256) k1_corr_e0(const float* __restrict__ x) {
    const int bm = blockIdx.x;
    __shared__ float xst[D * 33];
    __shared__ float S[NN];

    const int tid = threadIdx.x;
    const float* xt = x + (size_t)bm * (NN * D);

    for (int i = tid; i < NN * D; i += 256) {
        int n = i >> 8, d = i & 255;
        xst[d * 33 + n] = xt[i];
    }
    __syncthreads();

    const int w = tid >> 5, lane = tid & 31;

    for (int r = 0; r < 4; r++) {
        int n = w * 4 + r;
        float s = 0.f;
        #pragma unroll
        for (int j = 0; j < 8; j++) s += xst[(lane + 32 * j) * 33 + n];
        #pragma unroll
        for (int off = 16; off; off >>= 1) s += __shfl_xor_sync(0xffffffffu, s, off);
        if (lane == 0) S[n] = s;
    }
    __syncthreads();

    const float Sk = S[lane];
    float dotr[4] = {0.f, 0.f, 0.f, 0.f}, eq[4] = {0.f, 0.f, 0.f, 0.f};

    #pragma unroll 4
    for (int d = 0; d < D; d++) {
        const float xk = xst[d * 33 + lane];   // conflict-free
        #pragma unroll
        for (int i = 0; i < 4; i++) {
            const float xn = xst[d * 33 + w + 8 * i];  // broadcast
            dotr[i] += xn * xk;
            eq[i]   += (xn == xk) ? xk : 0.f;
        }
    }

    #pragma unroll
    for (int i = 0; i < 4; i++) {
        const int n = w + 8 * i;
        const int p = n * NN + lane;
        g_cov[bm * C + p] = dotr[i] - S[n] * Sk * (1.f / 256.f);
        g_ef[bm * C + p]  = (S[n] + 2.f * Sk - eq[i]) * (1.f / (2.f * D));
    }
}

// ---------------------------------------------------------------------------
// Kernel 2a: h[b,m][o] = relu( sum_c W1[o][c] * ef[b,m][c] )
// grid (16 o-tiles, 8 b), 384 threads (warp = m). W tile (32x1024, 128KB) and
// ef (12x1024, 48KB) staged in dynamic smem, all loads coalesced.
// Lanes cover c (LDS.128 conflict-free), butterfly reduce per output.
// ---------------------------------------------------------------------------
__global__ void __launch_bounds__(384) k2a_gemm1(const float* __restrict__ W1) {
    extern __shared__ float sm1[];
    float* ws  = sm1;               // [32][1024]
    float* efs = sm1 + 32 * 1024;   // [12][1024]

    const int ot = blockIdx.x, b = blockIdx.y;
    const int tid = threadIdx.x;

    const float4* w1g = (const float4*)(W1 + (size_t)(ot * 32) * C);
    float4* ws4 = (float4*)ws;
    for (int i = tid; i < 32 * C / 4; i += 384) ws4[i] = w1g[i];

    const float4* efg = (const float4*)(g_ef + (size_t)b * M * C);
    float4* efs4 = (float4*)efs;
    for (int i = tid; i < M * C / 4; i += 384) efs4[i] = efg[i];
    __syncthreads();

    const int m = tid >> 5, lane = tid & 31;

    float4 er[8];
    #pragma unroll
    for (int t = 0; t < 8; t++) er[t] = ((const float4*)efs)[m * 256 + t * 32 + lane];

    float res = 0.f;
    #pragma unroll 4
    for (int o = 0; o < 32; o++) {
        float ax = 0.f, ay = 0.f, az = 0.f, aw = 0.f;
        #pragma unroll
        for (int t = 0; t < 8; t++) {
            const float4 wv = ((const float4*)ws)[o * 256 + t * 32 + lane];
            ax += wv.x * er[t].x; ay += wv.y * er[t].y;
            az += wv.z * er[t].z; aw += wv.w * er[t].w;
        }
        float v = (ax + ay) + (az + aw);
        #pragma unroll
        for (int off = 16; off; off >>= 1) v += __shfl_xor_sync(0xffffffffu, v, off);
        if (lane == o) res = v;
    }
    g_h[((size_t)b * M + m) * CH + ot * 32 + lane] = fmaxf(res, 0.f);
}

// ---------------------------------------------------------------------------
// Kernel 2b: e2[b,m][c] = sum_o W2[c][o] * h[b,m][o]
// grid (16 c-tiles of 64, 8 b), 384 threads. Same scheme.
// ---------------------------------------------------------------------------
__global__ void __launch_bounds__(384) k2b_gemm2(const float* __restrict__ W2) {
    extern __shared__ float sm2[];
    float* ws = sm2;               // [64][512]
    float* hs = sm2 + 64 * 512;    // [12][512]

    const int ct = blockIdx.x, b = blockIdx.y;
    const int tid = threadIdx.x;

    const float4* w2g = (const float4*)(W2 + (size_t)(ct * 64) * CH);
    float4* ws4 = (float4*)ws;
    for (int i = tid; i < 64 * CH / 4; i += 384) ws4[i] = w2g[i];

    const float4* hg = (const float4*)(g_h + (size_t)b * M * CH);
    float4* hs4 = (float4*)hs;
    for (int i = tid; i < M * CH / 4; i += 384) hs4[i] = hg[i];
    __syncthreads();

    const int m = tid >> 5, lane = tid & 31;

    float4 hr[4];
    #pragma unroll
    for (int t = 0; t < 4; t++) hr[t] = ((const float4*)hs)[m * 128 + t * 32 + lane];

    float res0 = 0.f, res1 = 0.f;
    #pragma unroll 4
    for (int cl = 0; cl < 64; cl++) {
        float ax = 0.f, ay = 0.f, az = 0.f, aw = 0.f;
        #pragma unroll
        for (int t = 0; t < 4; t++) {
            const float4 wv = ((const float4*)ws)[cl * 128 + t * 32 + lane];
            ax += wv.x * hr[t].x; ay += wv.y * hr[t].y;
            az += wv.z * hr[t].z; aw += wv.w * hr[t].w;
        }
        float v = (ax + ay) + (az + aw);
        #pragma unroll
        for (int off = 16; off; off >>= 1) v += __shfl_xor_sync(0xffffffffu, v, off);
        if ((cl & 31) == lane) { if (cl < 32) res0 = v; else res1 = v; }
    }
    float* e2p = g_e2 + ((size_t)b * M + m) * C + ct * 64;
    e2p[lane]      = res0;
    e2p[32 + lane] = res1;
}

// ---------------------------------------------------------------------------
// Kernel 3: grid (bm, d-half), 128 threads. sigmoid+mask+softmax (redundant
// across the two d-halves, cheap), then out[n][d] = sum_k att[n][k]*x[k][d].
// ---------------------------------------------------------------------------
__global__ void __launch_bounds__(128) k3_softmax_av(const float* __restrict__ x,
                                                     float* __restrict__ out) {
    const int bm = blockIdx.x;
    const int d0 = blockIdx.y * 128;
    __shared__ float xs[NN * 128];  // 16 KB, [k*128 + dd]
    __shared__ float att[C];        // 4 KB

    const int tid = threadIdx.x;
    const float* xt = x + (size_t)bm * (NN * D);

    for (int i = tid; i < NN * 128; i += 128) {
        int k = i >> 7, dd = i & 127;
        xs[i] = xt[k * D + d0 + dd];
    }
    for (int i = tid; i < C; i += 128) {
        const float cv = g_cov[bm * C + i];
        const float v  = g_e2[bm * C + i];
        const float e  = 1.f / (1.f + expf(-v));
        att[i] = (cv > 0.f) ? e : -1e12f;
    }
    __syncthreads();

    const int w = tid >> 5, lane = tid & 31;
    for (int r = 0; r < 8; r++) {
        const int n = w * 8 + r;
        const float v = att[n * NN + lane];
        float mx = v;
        #pragma unroll
        for (int off = 16; off; off >>= 1) mx = fmaxf(mx, __shfl_xor_sync(0xffffffffu, mx, off));
        const float ev = expf(v - mx);
        float s = ev;
        #pragma unroll
        for (int off = 16; off; off >>= 1) s += __shfl_xor_sync(0xffffffffu, s, off);
        att[n * NN + lane] = ev / s;
    }
    __syncthreads();

    float acc[NN];
    #pragma unroll
    for (int n = 0; n < NN; n++) acc[n] = 0.f;

    for (int k = 0; k < NN; k++) {
        const float xv = xs[k * 128 + tid];   // conflict-free
        #pragma unroll
        for (int n = 0; n < NN; n++)
            acc[n] += att[n * NN + k] * xv;   // broadcast
    }

    float* ot = out + (size_t)bm * (NN * D) + d0;
    #pragma unroll
    for (int n = 0; n < NN; n++) ot[n * D + tid] = acc[n];
}

// ---------------------------------------------------------------------------
extern "C" void kernel_launch(void* const* d_in, const int* in_sizes, int n_in,
                              void* d_out, int out_size) {
    const float* x  = (const float*)d_in[0];
    const float* W1 = (const float*)d_in[1];
    const float* W2 = (const float*)d_in[2];
    float* out = (float*)d_out;

    const int smem1 = (32 * C + M * C) * sizeof(float);   // 180224 B
    const int smem2 = (64 * CH + M * CH) * sizeof(float); // 155648 B
    cudaFuncSetAttribute(k2a_gemm1, cudaFuncAttributeMaxDynamicSharedMemorySize, smem1);
    cudaFuncSetAttribute(k2b_gemm2, cudaFuncAttributeMaxDynamicSharedMemorySize, smem2);

    k1_corr_e0<<<B * M, 256>>>(x);
    k2a_gemm1<<<dim3(CH / 32, B), 384, smem1>>>(W1);
    k2b_gemm2<<<dim3(C / 64, B), 384, smem2>>>(W2);
    k3_softmax_av<<<dim3(B * M, 2), 128>>>(x, out);
}

// round 3
// speedup vs baseline: 3.9557x; 1.4675x over previous
#include <cuda_runtime.h>
#include <math.h>

#define B 8
#define M 12
#define NN 32
#define D 256
#define C 1024      // N*N
#define CH 512      // C/R
#define BM 96

// Scratch (allocation-free rule: device globals)
__device__ float g_cov[BM * C];   // centered cov (sign -> mask)
__device__ float g_U[NN * CH];    // [n][o] collapsed-GEMM1 weights
__device__ float g_h[BM * CH];    // hidden after relu
__device__ float g_att[BM * C];   // final attention weights
__device__ int   g_uflag;         // U-ready counter (reset by k3 each run)

// ---------------------------------------------------------------------------
// kMix: blocks [96,160): U[o][n] = rowsum+2*colsum-diag of W1 row o.
//       blocks [0,96):   per bm: S, cov sign; spin on U; h = relu(U·S/512).
// ---------------------------------------------------------------------------
__global__ void __launch_bounds__(256) kmix(const float* __restrict__ x,
                                            const float* __restrict__ W1) {
    const int tid = threadIdx.x;
    const int w = tid >> 5, lane = tid & 31;

    if (blockIdx.x >= BM) {
        // ---- kU: one warp per output row o ----
        const int o = (blockIdx.x - BM) * 8 + w;
        const float* row = W1 + (size_t)o * C;
        float r[32];
        #pragma unroll
        for (int j = 0; j < 32; j++) r[j] = row[j * 32 + lane];  // (n=j, k=lane)

        float cs = 0.f;                    // colsum for n = lane
        #pragma unroll
        for (int j = 0; j < 32; j++) cs += r[j];

        float rs = 0.f, dg = 0.f;          // rowsum, diag selected at lane = n
        #pragma unroll
        for (int j = 0; j < 32; j++) {
            float s = r[j];
            #pragma unroll
            for (int off = 16; off; off >>= 1) s += __shfl_xor_sync(0xffffffffu, s, off);
            if (lane == j) { rs = s; dg = r[j]; }  // r[j]@lane==j is W1[o][j*32+j]
        }
        g_U[lane * CH + o] = rs + 2.f * cs - dg;

        __threadfence();
        __syncthreads();
        if (tid == 0) atomicAdd(&g_uflag, 1);
        return;
    }

    // ---- k1a: per (b,m) ----
    const int bm = blockIdx.x;
    __shared__ float xst[D * 33];
    __shared__ float S[NN];

    const float* xt = x + (size_t)bm * (NN * D);
    for (int i = tid; i < NN * D; i += 256) {
        int n = i >> 8, d = i & 255;
        xst[d * 33 + n] = xt[i];
    }
    __syncthreads();

    for (int r = 0; r < 4; r++) {
        int n = w * 4 + r;
        float s = 0.f;
        #pragma unroll
        for (int j = 0; j < 8; j++) s += xst[(lane + 32 * j) * 33 + n];
        #pragma unroll
        for (int off = 16; off; off >>= 1) s += __shfl_xor_sync(0xffffffffu, s, off);
        if (lane == 0) S[n] = s;
    }
    __syncthreads();

    const float Sk = S[lane];
    float dotr[4] = {0.f, 0.f, 0.f, 0.f};
    #pragma unroll 4
    for (int d = 0; d < D; d++) {
        const float xk = xst[d * 33 + lane];        // conflict-free
        #pragma unroll
        for (int i = 0; i < 4; i++)
            dotr[i] += xst[d * 33 + w + 8 * i] * xk; // broadcast
    }
    #pragma unroll
    for (int i = 0; i < 4; i++) {
        const int n = w + 8 * i;
        g_cov[bm * C + n * NN + lane] = dotr[i] - S[n] * Sk * (1.f / 256.f);
    }

    // wait for U, then h = relu(sum_n U[n][o] * S[n] / 512)
    if (tid == 0) { while (atomicAdd(&g_uflag, 0) < 64) { } }
    __syncthreads();

    #pragma unroll
    for (int t = 0; t < 2; t++) {
        const int o = tid + t * 256;
        float acc = 0.f;
        #pragma unroll
        for (int n = 0; n < NN; n++)
            acc += g_U[n * CH + o] * S[n];           // coalesced over o
        g_h[bm * CH + o] = fmaxf(acc * (1.f / 512.f), 0.f);
    }
}

// ---------------------------------------------------------------------------
// k2: grid (16 ct, 8 b), 384 thr (warp = m). e2 for c-tile of 64 (= att rows
// 2ct, 2ct+1), then fused sigmoid + mask + warp softmax (no max pass: diag
// always unmasked and values in (0,1)). Writes final att.
// ---------------------------------------------------------------------------
__global__ void __launch_bounds__(384) k2_gemm_softmax(const float* __restrict__ W2) {
    const int ct = blockIdx.x, b = blockIdx.y;
    const int tid = threadIdx.x;
    const int m = tid >> 5, lane = tid & 31;
    const int bm = b * M + m;

    float4 h4[4];
    #pragma unroll
    for (int jj = 0; jj < 4; jj++)
        h4[jj] = ((const float4*)(g_h + (size_t)bm * CH))[jj * 32 + lane];

    float res0 = 0.f, res1 = 0.f;
    #pragma unroll 2
    for (int cl = 0; cl < 64; cl++) {
        const int c = ct * 64 + cl;
        const float4* w2r = (const float4*)(W2 + (size_t)c * CH);
        float ax = 0.f, ay = 0.f, az = 0.f, aw = 0.f;
        #pragma unroll
        for (int jj = 0; jj < 4; jj++) {
            const float4 wv = w2r[jj * 32 + lane];   // coalesced, L1-hit across warps
            ax += wv.x * h4[jj].x; ay += wv.y * h4[jj].y;
            az += wv.z * h4[jj].z; aw += wv.w * h4[jj].w;
        }
        float v = (ax + ay) + (az + aw);
        #pragma unroll
        for (int off = 16; off; off >>= 1) v += __shfl_xor_sync(0xffffffffu, v, off);
        if (cl < 32) { if (cl == lane) res0 = v; }
        else         { if (cl - 32 == lane) res1 = v; }
    }

    // rows n0 = 2ct (res0), n1 = 2ct+1 (res1); k = lane
    const int n0 = ct * 2, n1 = ct * 2 + 1;
    const float cv0 = g_cov[bm * C + n0 * NN + lane];
    const float cv1 = g_cov[bm * C + n1 * NN + lane];

    const float sg0 = 1.f / (1.f + __expf(-res0));
    const float sg1 = 1.f / (1.f + __expf(-res1));
    float ev0 = (cv0 > 0.f) ? __expf(sg0) : 0.f;
    float ev1 = (cv1 > 0.f) ? __expf(sg1) : 0.f;

    float s0 = ev0, s1 = ev1;
    #pragma unroll
    for (int off = 16; off; off >>= 1) {
        s0 += __shfl_xor_sync(0xffffffffu, s0, off);
        s1 += __shfl_xor_sync(0xffffffffu, s1, off);
    }
    g_att[bm * C + n0 * NN + lane] = ev0 / s0;
    g_att[bm * C + n1 * NN + lane] = ev1 / s1;
}

// ---------------------------------------------------------------------------
// k3: per bm, 256 thr. Pure AV: out[n][d=tid] = sum_k att[n][k] * x[k][d].
// x row cached in 32 regs; att rows via LDS.128 broadcast.
// Also resets g_uflag for the next graph replay.
// ---------------------------------------------------------------------------
__global__ void __launch_bounds__(256) k3_av(const float* __restrict__ x,
                                             float* __restrict__ out) {
    const int bm = blockIdx.x;
    __shared__ float xs[NN * D];   // 32 KB
    __shared__ float att[C];       // 4 KB

    if (blockIdx.x == 0 && threadIdx.x == 0) atomicExch(&g_uflag, 0);

    const int tid = threadIdx.x;
    const float4* xt4 = (const float4*)(x + (size_t)bm * (NN * D));
    float4* xs4 = (float4*)xs;
    #pragma unroll
    for (int i = 0; i < 8; i++) xs4[tid + i * 256] = xt4[tid + i * 256];

    ((float4*)att)[tid] = ((const float4*)(g_att + (size_t)bm * C))[tid];
    __syncthreads();

    float xv[NN];
    #pragma unroll
    for (int k = 0; k < NN; k++) xv[k] = xs[k * D + tid];

    float* ot = out + (size_t)bm * (NN * D);
    #pragma unroll 4
    for (int n = 0; n < NN; n++) {
        const float4* arow = (const float4*)(att + n * NN);
        float acc = 0.f;
        #pragma unroll
        for (int kk = 0; kk < 8; kk++) {
            const float4 a4 = arow[kk];            // broadcast LDS.128
            acc += a4.x * xv[kk * 4 + 0] + a4.y * xv[kk * 4 + 1]
                 + a4.z * xv[kk * 4 + 2] + a4.w * xv[kk * 4 + 3];
        }
        ot[n * D + tid] = acc;
    }
}

// ---------------------------------------------------------------------------
extern "C" void kernel_launch(void* const* d_in, const int* in_sizes, int n_in,
                              void* d_out, int out_size) {
    const float* x  = (const float*)d_in[0];
    const float* W1 = (const float*)d_in[1];
    const float* W2 = (const float*)d_in[2];
    float* out = (float*)d_out;

    kmix<<<BM + 64, 256>>>(x, W1);
    k2_gemm_softmax<<<dim3(16, B), 384>>>(W2);
    k3_av<<<BM, 256>>>(x, out);
}